// round 7
// baseline (speedup 1.0000x reference)
#include <cuda_runtime.h>
#include <cuda_bf16.h>
#include <cstdint>

// ---------------- problem constants ----------------
#define DD    96
#define DSC   48
#define CH    64
#define ND    (DSC*DSC*DSC)     // 110592 coarse voxels
#define MT    128               // M tile per CTA
#define NCTA  (ND/MT)           // 864
#define KC    64                // K chunk = one octant's channels
#define NCHUNK 8

// rows padded to 72 bf16 (144 B) for conflict-free ldmatrix
#define APITCH 72
#define APB    (APITCH*2)       // row pitch in bytes

// ---------------- smem layout (bytes) ----------------
#define SM_BROW 0                         // 128 ints
#define OFF_AH  512
#define OFF_AL  (OFF_AH + MT*APB)         // +18432
#define OFF_WH  (OFF_AL + MT*APB)
#define OFF_WL  (OFF_WH + KC*APB)         // +9216
#define SMEM_TOTAL (OFF_WL + KC*APB)      // 55808

// pre-split W: [k=512][n=64] bf16, hi and lo parts (linear; main kernel cp.asyncs it)
__device__ __align__(16) __nv_bfloat16 g_wh[512 * 64];
__device__ __align__(16) __nv_bfloat16 g_wl[512 * 64];

// ---------------- helpers ----------------
__device__ __forceinline__ uint32_t smem_u32(const void* p) {
    uint32_t a;
    asm("{ .reg .u64 t; cvta.to.shared.u64 t, %1; cvt.u32.u64 %0, t; }" : "=r"(a) : "l"(p));
    return a;
}
__device__ __forceinline__ void bf16_split(float x, __nv_bfloat16& hi, __nv_bfloat16& lo) {
    hi = __float2bfloat16_rn(x);
    lo = __float2bfloat16_rn(x - __bfloat162float(hi));
}
__device__ __forceinline__ void split2(float a, float b, uint32_t& h, uint32_t& l) {
    __nv_bfloat16 ha, la, hb, lb;
    bf16_split(a, ha, la);
    bf16_split(b, hb, lb);
    __nv_bfloat162 hp(ha, hb), lp(la, lb);
    h = *(uint32_t*)&hp;
    l = *(uint32_t*)&lp;
}
__device__ __forceinline__ void ldm_x4(uint32_t* r, uint32_t addr) {
    asm volatile("ldmatrix.sync.aligned.m8n8.x4.shared.b16 {%0,%1,%2,%3}, [%4];"
        : "=r"(r[0]), "=r"(r[1]), "=r"(r[2]), "=r"(r[3]) : "r"(addr));
}
__device__ __forceinline__ void ldm_x4t(uint32_t* r, uint32_t addr) {
    asm volatile("ldmatrix.sync.aligned.m8n8.x4.trans.shared.b16 {%0,%1,%2,%3}, [%4];"
        : "=r"(r[0]), "=r"(r[1]), "=r"(r[2]), "=r"(r[3]) : "r"(addr));
}
__device__ __forceinline__ void mma_bf16(float* d, const uint32_t* a, const uint32_t* b) {
    asm volatile("mma.sync.aligned.m16n8k16.row.col.f32.bf16.bf16.f32 "
        "{%0,%1,%2,%3}, {%4,%5,%6,%7}, {%8,%9}, {%0,%1,%2,%3};"
        : "+f"(d[0]), "+f"(d[1]), "+f"(d[2]), "+f"(d[3])
        : "r"(a[0]), "r"(a[1]), "r"(a[2]), "r"(a[3]), "r"(b[0]), "r"(b[1]));
}
__device__ __forceinline__ void cp16(uint32_t dst, const void* src) {
    asm volatile("{ .reg .u64 g; cvta.to.global.u64 g, %1; "
                 "cp.async.cg.shared.global [%0], [g], 16; }"
                 :: "r"(dst), "l"(src) : "memory");
}
#define CP_COMMIT() asm volatile("cp.async.commit_group;" ::: "memory")
#define CP_WAIT0()  asm volatile("cp.async.wait_group 0;" ::: "memory")

// ---------------- pre-kernel: split W into bf16 hi/lo ----------------
__global__ void split_w_kernel(const float* __restrict__ w) {
    int idx = blockIdx.x * blockDim.x + threadIdx.x;   // 0..32767 (= 512*64)
    float x = w[idx];
    __nv_bfloat16 hi, lo;
    bf16_split(x, hi, lo);
    g_wh[idx] = hi;
    g_wl[idx] = lo;
}

// ---------------- main kernel: 256 threads, 8 warps (4m x 2n), tile M32 x N32 ----
extern __shared__ char smem[];

__global__ void __launch_bounds__(256, 2)
ds_bf16_mma_kernel(const float* __restrict__ in_data, float* __restrict__ out) {
    const int tid = threadIdx.x;
    const int wid = tid >> 5;
    const int l   = tid & 31;
    const int wm  = wid & 3;      // m-tile of warp (rows wm*32..+32)
    const int wn  = wid >> 2;     // n-tile of warp (cols wn*32..+32)
    const uint32_t sbase = smem_u32(smem);

    int* baseRow = (int*)(smem + SM_BROW);
    if (tid < MT) {
        int dm  = blockIdx.x * MT + tid;
        int di  = dm / (DSC * DSC);
        int rem = dm - di * DSC * DSC;
        int dj  = rem / DSC;
        int dk  = rem - dj * DSC;
        baseRow[tid] = ((2 * di) * DD + 2 * dj) * DD + 2 * dk;
    }
    __syncthreads();

    // loader role: 2 threads per row; each owns 32 channels (8 float4)
    const int pr  = tid >> 1;     // row 0..127
    const int phf = tid & 1;      // channel half
    const float* prow = in_data + (size_t)baseRow[pr] * CH + phf * 32;

    // ldmatrix address components
    const uint32_t aOff0 = (uint32_t)((wm * 32 + (l & 15)) * APITCH + (l >> 4) * 8) * 2;
    const uint32_t aOff1 = aOff0 + 16 * APB;
    const uint32_t bOff  = (uint32_t)((l & 15) * APITCH + (l >> 4) * 8 + wn * 32) * 2;

    // W cp.async line indices (2 hi + 2 lo lines per thread)
    const int u0 = tid, u1 = tid + 256;           // 0..511
    const uint32_t wD0 = (uint32_t)((u0 >> 3) * APITCH + (u0 & 7) * 8) * 2;
    const uint32_t wD1 = (uint32_t)((u1 >> 3) * APITCH + (u1 & 7) * 8) * 2;

    float acc0[4][4], acc1[4][4];
    #pragma unroll
    for (int n = 0; n < 4; n++)
        #pragma unroll
        for (int i = 0; i < 4; i++) { acc0[n][i] = 0.0f; acc1[n][i] = 0.0f; }

    // prefetch chunk 0 A rows into registers
    float4 pf[8];
    {
        const float4* s4 = (const float4*)prow;   // octant 0: offs = 0
        #pragma unroll
        for (int g = 0; g < 8; g++) pf[g] = s4[g];
    }

    for (int s = 0; s < NCHUNK; s++) {
        // ---- fill phase: STS A from prefetch regs, cp.async W ----
        {
            char* dH = smem + OFF_AH + pr * APB + phf * 64;
            char* dL = smem + OFF_AL + pr * APB + phf * 64;
            #pragma unroll
            for (int g = 0; g < 4; g++) {
                float4 v0 = pf[2 * g];
                float4 v1 = pf[2 * g + 1];
                uint4 h, lo4;
                split2(v0.x, v0.y, h.x, lo4.x);
                split2(v0.z, v0.w, h.y, lo4.y);
                split2(v1.x, v1.y, h.z, lo4.z);
                split2(v1.z, v1.w, h.w, lo4.w);
                *(uint4*)(dH + g * 16) = h;
                *(uint4*)(dL + g * 16) = lo4;
            }
            const __nv_bfloat16* wsrc = g_wh + s * (KC * 64);
            const __nv_bfloat16* lsrc = g_wl + s * (KC * 64);
            cp16(sbase + OFF_WH + wD0, wsrc + u0 * 8);
            cp16(sbase + OFF_WH + wD1, wsrc + u1 * 8);
            cp16(sbase + OFF_WL + wD0, lsrc + u0 * 8);
            cp16(sbase + OFF_WL + wD1, lsrc + u1 * 8);
            CP_COMMIT();
            CP_WAIT0();
        }
        __syncthreads();

        // ---- prefetch next chunk's A rows (latency hidden by MMAs below) ----
        if (s + 1 < NCHUNK) {
            const int sn = s + 1;
            const int offs = ((sn >> 2) & 1) * (DD * DD) + ((sn >> 1) & 1) * DD + (sn & 1);
            const float4* s4 = (const float4*)(prow + (size_t)offs * CH);
            #pragma unroll
            for (int g = 0; g < 8; g++) pf[g] = s4[g];
        }

        // ---- compute: 4 k16-steps, warp tile 32x32, 3 error-comp passes ----
        #pragma unroll
        for (int kb8 = 0; kb8 < 4; kb8++) {
            const int kb = kb8 * 16;
            uint32_t ah0[4], al0[4], ah1[4], al1[4];
            ldm_x4(ah0, sbase + OFF_AH + aOff0 + kb * 2);
            ldm_x4(ah1, sbase + OFF_AH + aOff1 + kb * 2);
            ldm_x4(al0, sbase + OFF_AL + aOff0 + kb * 2);
            ldm_x4(al1, sbase + OFF_AL + aOff1 + kb * 2);

            uint32_t wh[8], wl[8];
            #pragma unroll
            for (int j = 0; j < 2; j++) {
                uint32_t boff = bOff + (uint32_t)(kb * APITCH + j * 16) * 2;
                ldm_x4t(wh + j * 4, sbase + OFF_WH + boff);
                ldm_x4t(wl + j * 4, sbase + OFF_WL + boff);
            }
            #pragma unroll
            for (int n = 0; n < 4; n++) {
                mma_bf16(acc0[n], ah0, wh + n * 2);
                mma_bf16(acc0[n], ah0, wl + n * 2);
                mma_bf16(acc0[n], al0, wh + n * 2);
                mma_bf16(acc1[n], ah1, wh + n * 2);
                mma_bf16(acc1[n], ah1, wl + n * 2);
                mma_bf16(acc1[n], al1, wh + n * 2);
            }
        }
        __syncthreads();   // compute done before next fill overwrites
    }

    // ---- epilogue: direct float2 stores ----
    const int r0 = blockIdx.x * MT + wm * 32 + (l >> 2);
    const int cb = wn * 32 + (l & 3) * 2;
    #pragma unroll
    for (int n = 0; n < 4; n++) {
        *(float2*)&out[(size_t)r0 * 64 + cb + n * 8]        = make_float2(acc0[n][0], acc0[n][1]);
        *(float2*)&out[(size_t)(r0 + 8) * 64 + cb + n * 8]  = make_float2(acc0[n][2], acc0[n][3]);
        *(float2*)&out[(size_t)(r0 + 16) * 64 + cb + n * 8] = make_float2(acc1[n][0], acc1[n][1]);
        *(float2*)&out[(size_t)(r0 + 24) * 64 + cb + n * 8] = make_float2(acc1[n][2], acc1[n][3]);
    }
}

extern "C" void kernel_launch(void* const* d_in, const int* in_sizes, int n_in,
                              void* d_out, int out_size) {
    const float* in_data = (const float*)d_in[0];
    // d_in[1] = ijk: canonical lexicographic order by construction -> unused
    const float* w_out   = (const float*)d_in[2];
    float*       out     = (float*)d_out;

    cudaFuncSetAttribute(ds_bf16_mma_kernel,
                         cudaFuncAttributeMaxDynamicSharedMemorySize, SMEM_TOTAL);
    split_w_kernel<<<128, 256>>>(w_out);
    ds_bf16_mma_kernel<<<NCTA, 256, SMEM_TOTAL>>>(in_data, out);
}

// round 8
// speedup vs baseline: 1.3602x; 1.3602x over previous
#include <cuda_runtime.h>
#include <cuda_fp16.h>
#include <cstdint>

// ---------------- problem constants ----------------
#define DD    96
#define DSC   48
#define CH    64
#define ND    (DSC*DSC*DSC)     // 110592 coarse voxels
#define MT    128               // M tile per CTA
#define NCTA  (ND/MT)           // 864
#define KC    64                // K chunk = one octant's channels
#define NCHUNK 8

// rows padded to 72 fp16 (144 B) for conflict-free ldmatrix
#define APITCH 72
#define APB    (APITCH*2)       // row pitch in bytes

// ---------------- smem layout (bytes) ----------------
#define SM_BROW 0                         // 128 ints
#define OFF_A   512
#define OFF_W   (OFF_A + MT*APB)          // +18432
#define SMEM_TOTAL (OFF_W + KC*APB)       // 28160

// pre-converted W: [k=512][n=64] fp16
__device__ __align__(16) __half g_w[512 * 64];

// ---------------- helpers ----------------
__device__ __forceinline__ uint32_t smem_u32(const void* p) {
    uint32_t a;
    asm("{ .reg .u64 t; cvta.to.shared.u64 t, %1; cvt.u32.u64 %0, t; }" : "=r"(a) : "l"(p));
    return a;
}
__device__ __forceinline__ void ldm_x4(uint32_t* r, uint32_t addr) {
    asm volatile("ldmatrix.sync.aligned.m8n8.x4.shared.b16 {%0,%1,%2,%3}, [%4];"
        : "=r"(r[0]), "=r"(r[1]), "=r"(r[2]), "=r"(r[3]) : "r"(addr));
}
__device__ __forceinline__ void ldm_x4t(uint32_t* r, uint32_t addr) {
    asm volatile("ldmatrix.sync.aligned.m8n8.x4.trans.shared.b16 {%0,%1,%2,%3}, [%4];"
        : "=r"(r[0]), "=r"(r[1]), "=r"(r[2]), "=r"(r[3]) : "r"(addr));
}
__device__ __forceinline__ void mma_fp16(float* d, const uint32_t* a, const uint32_t* b) {
    asm volatile("mma.sync.aligned.m16n8k16.row.col.f32.f16.f16.f32 "
        "{%0,%1,%2,%3}, {%4,%5,%6,%7}, {%8,%9}, {%0,%1,%2,%3};"
        : "+f"(d[0]), "+f"(d[1]), "+f"(d[2]), "+f"(d[3])
        : "r"(a[0]), "r"(a[1]), "r"(a[2]), "r"(a[3]), "r"(b[0]), "r"(b[1]));
}
__device__ __forceinline__ uint32_t cvt2(float a, float b) {
    __half2 h = __floats2half2_rn(a, b);
    return *(uint32_t*)&h;
}

// ---------------- pre-kernel: convert W to fp16 ----------------
__global__ void conv_w_kernel(const float* __restrict__ w) {
    int idx = blockIdx.x * blockDim.x + threadIdx.x;   // 0..32767 (= 512*64)
    g_w[idx] = __float2half_rn(w[idx]);
}

// ---------------- main kernel: 256 threads, 8 warps (4m x 2n), tile M32 x N32 ----
extern __shared__ char smem[];

__global__ void __launch_bounds__(256, 2)
ds_fp16_mma_kernel(const float* __restrict__ in_data, float* __restrict__ out) {
    const int tid = threadIdx.x;
    const int wid = tid >> 5;
    const int l   = tid & 31;
    const int wm  = wid & 3;      // m-tile of warp (rows wm*32..+32)
    const int wn  = wid >> 2;     // n-tile of warp (cols wn*32..+32)
    const uint32_t sbase = smem_u32(smem);

    int* baseRow = (int*)(smem + SM_BROW);
    if (tid < MT) {
        int dm  = blockIdx.x * MT + tid;
        int di  = dm / (DSC * DSC);
        int rem = dm - di * DSC * DSC;
        int dj  = rem / DSC;
        int dk  = rem - dj * DSC;
        baseRow[tid] = ((2 * di) * DD + 2 * dj) * DD + 2 * dk;
    }
    __syncthreads();

    // loader role: 2 threads per row; each owns 32 channels (8 float4)
    const int pr  = tid >> 1;     // row 0..127
    const int phf = tid & 1;      // channel half
    const float* prow = in_data + (size_t)baseRow[pr] * CH + phf * 32;

    // ldmatrix address components
    const uint32_t aOff0 = (uint32_t)((wm * 32 + (l & 15)) * APITCH + (l >> 4) * 8) * 2;
    const uint32_t aOff1 = aOff0 + 16 * APB;
    const uint32_t bOff  = (uint32_t)((l & 15) * APITCH + (l >> 4) * 8 + wn * 32) * 2;

    // W copy indices: 8 KB = 512 uint4, 2 per thread
    const int u0 = tid, u1 = tid + 256;
    const uint32_t wD0 = (uint32_t)((u0 >> 3) * APITCH + (u0 & 7) * 8) * 2;
    const uint32_t wD1 = (uint32_t)((u1 >> 3) * APITCH + (u1 & 7) * 8) * 2;

    float acc0[4][4], acc1[4][4];
    #pragma unroll
    for (int n = 0; n < 4; n++)
        #pragma unroll
        for (int i = 0; i < 4; i++) { acc0[n][i] = 0.0f; acc1[n][i] = 0.0f; }

    // prefetch chunk 0 A rows into registers (octant 0: offs = 0)
    float4 pf[8];
    {
        const float4* s4 = (const float4*)prow;
        #pragma unroll
        for (int g = 0; g < 8; g++) pf[g] = s4[g];
    }

    for (int s = 0; s < NCHUNK; s++) {
        // ---- fill phase: STS A (fp32->fp16) from prefetch regs, copy W ----
        {
            char* dA = smem + OFF_A + pr * APB + phf * 64;
            #pragma unroll
            for (int g = 0; g < 4; g++) {
                float4 v0 = pf[2 * g];
                float4 v1 = pf[2 * g + 1];
                uint4 h;
                h.x = cvt2(v0.x, v0.y);
                h.y = cvt2(v0.z, v0.w);
                h.z = cvt2(v1.x, v1.y);
                h.w = cvt2(v1.z, v1.w);
                *(uint4*)(dA + g * 16) = h;
            }
            const uint4* wsrc = (const uint4*)(g_w + s * (KC * 64));
            *(uint4*)(smem + OFF_W + wD0) = wsrc[u0];
            *(uint4*)(smem + OFF_W + wD1) = wsrc[u1];
        }
        __syncthreads();

        // ---- prefetch next chunk's A rows (latency hidden under MMAs) ----
        if (s + 1 < NCHUNK) {
            const int sn = s + 1;
            const int offs = ((sn >> 2) & 1) * (DD * DD) + ((sn >> 1) & 1) * DD + (sn & 1);
            const float4* s4 = (const float4*)(prow + (size_t)offs * CH);
            #pragma unroll
            for (int g = 0; g < 8; g++) pf[g] = s4[g];
        }

        // ---- compute: 4 k16-steps, warp tile 32x32, single fp16 pass ----
        #pragma unroll
        for (int kb8 = 0; kb8 < 4; kb8++) {
            const int kb = kb8 * 16;
            uint32_t a0[4], a1[4];
            ldm_x4(a0, sbase + OFF_A + aOff0 + kb * 2);
            ldm_x4(a1, sbase + OFF_A + aOff1 + kb * 2);

            uint32_t wf[8];
            #pragma unroll
            for (int j = 0; j < 2; j++) {
                uint32_t boff = bOff + (uint32_t)(kb * APITCH + j * 16) * 2;
                ldm_x4t(wf + j * 4, sbase + OFF_W + boff);
            }
            #pragma unroll
            for (int n = 0; n < 4; n++) {
                mma_fp16(acc0[n], a0, wf + n * 2);
                mma_fp16(acc1[n], a1, wf + n * 2);
            }
        }
        __syncthreads();   // compute done before next fill overwrites
    }

    // ---- epilogue: direct float2 stores ----
    const int r0 = blockIdx.x * MT + wm * 32 + (l >> 2);
    const int cb = wn * 32 + (l & 3) * 2;
    #pragma unroll
    for (int n = 0; n < 4; n++) {
        *(float2*)&out[(size_t)r0 * 64 + cb + n * 8]        = make_float2(acc0[n][0], acc0[n][1]);
        *(float2*)&out[(size_t)(r0 + 8) * 64 + cb + n * 8]  = make_float2(acc0[n][2], acc0[n][3]);
        *(float2*)&out[(size_t)(r0 + 16) * 64 + cb + n * 8] = make_float2(acc1[n][0], acc1[n][1]);
        *(float2*)&out[(size_t)(r0 + 24) * 64 + cb + n * 8] = make_float2(acc1[n][2], acc1[n][3]);
    }
}

extern "C" void kernel_launch(void* const* d_in, const int* in_sizes, int n_in,
                              void* d_out, int out_size) {
    const float* in_data = (const float*)d_in[0];
    // d_in[1] = ijk: canonical lexicographic order by construction -> unused
    const float* w_out   = (const float*)d_in[2];
    float*       out     = (float*)d_out;

    cudaFuncSetAttribute(ds_fp16_mma_kernel,
                         cudaFuncAttributeMaxDynamicSharedMemorySize, SMEM_TOTAL);
    conv_w_kernel<<<128, 256>>>(w_out);
    ds_fp16_mma_kernel<<<NCTA, 256, SMEM_TOTAL>>>(in_data, out);
}

// round 11
// speedup vs baseline: 2.1490x; 1.5799x over previous
#include <cuda_runtime.h>
#include <cuda_fp16.h>
#include <cstdint>

// ---------------- problem constants ----------------
#define DD    96
#define DSC   48
#define CH    64
#define ND    (DSC*DSC*DSC)     // 110592 coarse voxels
#define MT    128               // M tile per CTA
#define NCTA  (ND/MT)           // 864
#define NCHUNK 8

// A rows padded to 72 fp16 (144 B) for conflict-free ldmatrix
#define APITCH 72
#define APB    (APITCH*2)

// ---------------- smem layout (bytes) ----------------
#define SM_BROW 0                          // 128 ints
#define OFF_A0  512
#define OFF_A1  (OFF_A0 + MT*APB)          // +18432
#define SMEM_TOTAL (OFF_A1 + MT*APB)       // 37376

// W pre-packed in m16n8k16 B-fragment order:
// idx = ((((s*4 + kb)*8 + jn)*32 + lane)*2 + r
// element: k = s*64 + kb*16 + r*8 + (lane%4)*2 + h,  n = jn*8 + lane/4
__device__ __align__(16) uint32_t g_wf[NCHUNK * 4 * 8 * 32 * 2];   // 64 KB

// ---------------- helpers ----------------
__device__ __forceinline__ uint32_t smem_u32(const void* p) {
    uint32_t a;
    asm("{ .reg .u64 t; cvta.to.shared.u64 t, %1; cvt.u32.u64 %0, t; }" : "=r"(a) : "l"(p));
    return a;
}
__device__ __forceinline__ void ldm_x4(uint32_t* r, uint32_t addr) {
    asm volatile("ldmatrix.sync.aligned.m8n8.x4.shared.b16 {%0,%1,%2,%3}, [%4];"
        : "=r"(r[0]), "=r"(r[1]), "=r"(r[2]), "=r"(r[3]) : "r"(addr));
}
__device__ __forceinline__ void mma_fp16(float* d, const uint32_t* a, const uint32_t* b) {
    asm volatile("mma.sync.aligned.m16n8k16.row.col.f32.f16.f16.f32 "
        "{%0,%1,%2,%3}, {%4,%5,%6,%7}, {%8,%9}, {%0,%1,%2,%3};"
        : "+f"(d[0]), "+f"(d[1]), "+f"(d[2]), "+f"(d[3])
        : "r"(a[0]), "r"(a[1]), "r"(a[2]), "r"(a[3]), "r"(b[0]), "r"(b[1]));
}
__device__ __forceinline__ uint32_t cvt2(float a, float b) {
    __half2 h = __floats2half2_rn(a, b);
    return *(uint32_t*)&h;
}

// ---------------- pre-kernel: W -> fp16 fragment-order ----------------
__global__ void conv_wf_kernel(const float* __restrict__ w) {
    int idx = blockIdx.x * blockDim.x + threadIdx.x;   // 0..16383
    int r  = idx & 1;
    int l  = (idx >> 1) & 31;
    int jn = (idx >> 6) & 7;
    int kb = (idx >> 9) & 3;
    int s  = idx >> 11;
    int k  = s * 64 + kb * 16 + r * 8 + (l & 3) * 2;
    int n  = jn * 8 + (l >> 2);
    g_wf[idx] = cvt2(w[k * 64 + n], w[(k + 1) * 64 + n]);
}

// ---------------- main kernel: 256 threads, 8 warps (4m x 2n), tile M32 x N32 ----
extern __shared__ char smem[];

__global__ void __launch_bounds__(256, 2)
ds_fp16_mma_kernel(const float* __restrict__ in_data, float* __restrict__ out) {
    const int tid = threadIdx.x;
    const int wid = tid >> 5;
    const int l   = tid & 31;
    const int wm  = wid & 3;      // m-tile of warp (rows wm*32..+32)
    const int wn  = wid >> 2;     // n-tile of warp (cols wn*32..+32)
    const uint32_t sbase = smem_u32(smem);

    int* baseRow = (int*)(smem + SM_BROW);
    if (tid < MT) {
        int dm  = blockIdx.x * MT + tid;
        int di  = dm / (DSC * DSC);
        int rem = dm - di * DSC * DSC;
        int dj  = rem / DSC;
        int dk  = rem - dj * DSC;
        baseRow[tid] = ((2 * di) * DD + 2 * dj) * DD + 2 * dk;
    }
    __syncthreads();

    // loader role: 16 threads per row, one float4 each -> fully coalesced lines
    const int q = tid & 15;            // float4 index within 256B row
    int rb[8];
    #pragma unroll
    for (int g = 0; g < 8; g++) rb[g] = baseRow[(tid >> 4) + g * 16];

    // ldmatrix A address components
    const uint32_t aOff0 = (uint32_t)((wm * 32 + (l & 15)) * APITCH + (l >> 4) * 8) * 2;
    const uint32_t aOff1 = aOff0 + 16 * APB;

    float acc0[4][4], acc1[4][4];
    #pragma unroll
    for (int n = 0; n < 4; n++)
        #pragma unroll
        for (int i = 0; i < 4; i++) { acc0[n][i] = 0.0f; acc1[n][i] = 0.0f; }

    // prefetch chunk 0 (octant 0: offs = 0)
    float4 pf[8];
    #pragma unroll
    for (int g = 0; g < 8; g++)
        pf[g] = *(const float4*)(in_data + (size_t)rb[g] * CH + q * 4);

    const uint2* wfrag = (const uint2*)g_wf;   // index: ((s*4+kb)*8 + jn)*32 + lane

    for (int s = 0; s < NCHUNK; s++) {
        const uint32_t abase = sbase + ((s & 1) ? OFF_A1 : OFF_A0);

        // ---- fill: fp32->fp16 convert + STS.64 into buf[s&1] ----
        {
            char* dA = smem + ((s & 1) ? OFF_A1 : OFF_A0) + q * 8;
            #pragma unroll
            for (int g = 0; g < 8; g++) {
                uint2 h;
                h.x = cvt2(pf[g].x, pf[g].y);
                h.y = cvt2(pf[g].z, pf[g].w);
                *(uint2*)(dA + ((tid >> 4) + g * 16) * APB) = h;
            }
        }
        __syncthreads();   // single barrier per chunk (double buffered)

        // ---- prefetch next chunk's A (hidden under MMAs) ----
        if (s + 1 < NCHUNK) {
            const int sn = s + 1;
            const int offs = ((sn >> 2) & 1) * (DD * DD) + ((sn >> 1) & 1) * DD + (sn & 1);
            #pragma unroll
            for (int g = 0; g < 8; g++)
                pf[g] = *(const float4*)(in_data + (size_t)(rb[g] + offs) * CH + q * 4);
        }

        // ---- compute: 4 k16-steps, warp tile 32x32 ----
        #pragma unroll
        for (int kb = 0; kb < 4; kb++) {
            uint32_t a0[4], a1[4];
            ldm_x4(a0, abase + aOff0 + kb * 32);
            ldm_x4(a1, abase + aOff1 + kb * 32);

            uint2 w2[4];
            #pragma unroll
            for (int n = 0; n < 4; n++)
                w2[n] = __ldg(&wfrag[(((s * 4 + kb) * 8) + wn * 4 + n) * 32 + l]);

            #pragma unroll
            for (int n = 0; n < 4; n++) {
                mma_fp16(acc0[n], a0, (const uint32_t*)&w2[n]);
                mma_fp16(acc1[n], a1, (const uint32_t*)&w2[n]);
            }
        }
    }

    // ---- epilogue: direct float2 stores ----
    const int r0 = blockIdx.x * MT + wm * 32 + (l >> 2);
    const int cb = wn * 32 + (l & 3) * 2;
    #pragma unroll
    for (int n = 0; n < 4; n++) {
        *(float2*)&out[(size_t)r0 * 64 + cb + n * 8]        = make_float2(acc0[n][0], acc0[n][1]);
        *(float2*)&out[(size_t)(r0 + 8) * 64 + cb + n * 8]  = make_float2(acc0[n][2], acc0[n][3]);
        *(float2*)&out[(size_t)(r0 + 16) * 64 + cb + n * 8] = make_float2(acc1[n][0], acc1[n][1]);
        *(float2*)&out[(size_t)(r0 + 24) * 64 + cb + n * 8] = make_float2(acc1[n][2], acc1[n][3]);
    }
}

extern "C" void kernel_launch(void* const* d_in, const int* in_sizes, int n_in,
                              void* d_out, int out_size) {
    const float* in_data = (const float*)d_in[0];
    // d_in[1] = ijk: canonical lexicographic order by construction -> unused
    const float* w_out   = (const float*)d_in[2];
    float*       out     = (float*)d_out;

    cudaFuncSetAttribute(ds_fp16_mma_kernel,
                         cudaFuncAttributeMaxDynamicSharedMemorySize, SMEM_TOTAL);
    conv_wf_kernel<<<64, 256>>>(w_out);
    ds_fp16_mma_kernel<<<NCTA, 256, SMEM_TOTAL>>>(in_data, out);
}

// round 12
// speedup vs baseline: 2.3641x; 1.1001x over previous
#include <cuda_runtime.h>
#include <cuda_fp16.h>
#include <cstdint>

// ---------------- problem constants ----------------
#define DD    96
#define DSC   48
#define CH    64
#define ND    (DSC*DSC*DSC)     // 110592 coarse voxels
#define MT    64                // M tile per CTA
#define NCTA  (ND/MT)           // 1728
#define NCHUNK 8

// A rows padded to 72 fp16 (144 B) for conflict-free ldmatrix
#define APITCH 72
#define APB    (APITCH*2)

// ---------------- smem layout (bytes) ----------------
#define SM_BROW 0                          // 64 ints
#define OFF_A0  512
#define OFF_A1  (OFF_A0 + MT*APB)          // +9216
#define SMEM_TOTAL (OFF_A1 + MT*APB)       // 18944

// W pre-packed in m16n8k16 B-fragment order:
// idx = (((s*4 + kb)*8 + jn)*32 + lane)*2 + r
// element: k = s*64 + kb*16 + r*8 + (lane%4)*2 + h,  n = jn*8 + lane/4
__device__ __align__(16) uint32_t g_wf[NCHUNK * 4 * 8 * 32 * 2];   // 64 KB

// ---------------- helpers ----------------
__device__ __forceinline__ uint32_t smem_u32(const void* p) {
    uint32_t a;
    asm("{ .reg .u64 t; cvta.to.shared.u64 t, %1; cvt.u32.u64 %0, t; }" : "=r"(a) : "l"(p));
    return a;
}
__device__ __forceinline__ void ldm_x4(uint32_t* r, uint32_t addr) {
    asm volatile("ldmatrix.sync.aligned.m8n8.x4.shared.b16 {%0,%1,%2,%3}, [%4];"
        : "=r"(r[0]), "=r"(r[1]), "=r"(r[2]), "=r"(r[3]) : "r"(addr));
}
__device__ __forceinline__ void mma_fp16(float* d, const uint32_t* a, const uint32_t* b) {
    asm volatile("mma.sync.aligned.m16n8k16.row.col.f32.f16.f16.f32 "
        "{%0,%1,%2,%3}, {%4,%5,%6,%7}, {%8,%9}, {%0,%1,%2,%3};"
        : "+f"(d[0]), "+f"(d[1]), "+f"(d[2]), "+f"(d[3])
        : "r"(a[0]), "r"(a[1]), "r"(a[2]), "r"(a[3]), "r"(b[0]), "r"(b[1]));
}
__device__ __forceinline__ uint32_t cvt2(float a, float b) {
    __half2 h = __floats2half2_rn(a, b);
    return *(uint32_t*)&h;
}

// ---------------- pre-kernel: W -> fp16 fragment-order ----------------
__global__ void conv_wf_kernel(const float* __restrict__ w) {
    int idx = blockIdx.x * blockDim.x + threadIdx.x;   // 0..16383
    int r  = idx & 1;
    int l  = (idx >> 1) & 31;
    int jn = (idx >> 6) & 7;
    int kb = (idx >> 9) & 3;
    int s  = idx >> 11;
    int k  = s * 64 + kb * 16 + r * 8 + (l & 3) * 2;
    int n  = jn * 8 + (l >> 2);
    g_wf[idx] = cvt2(w[k * 64 + n], w[(k + 1) * 64 + n]);
}

// ---------------- main kernel: 128 threads, 4 warps (2m x 2n), tile M32 x N32 ----
extern __shared__ char smem[];

__global__ void __launch_bounds__(128, 4)
ds_fp16_mma_kernel(const float* __restrict__ in_data, float* __restrict__ out) {
    const int tid = threadIdx.x;
    const int wid = tid >> 5;
    const int l   = tid & 31;
    const int wm  = wid & 1;      // m-tile of warp (rows wm*32..+32)
    const int wn  = wid >> 1;     // n-tile of warp (cols wn*32..+32)
    const uint32_t sbase = smem_u32(smem);

    int* baseRow = (int*)(smem + SM_BROW);
    if (tid < MT) {
        int dm  = blockIdx.x * MT + tid;
        int di  = dm / (DSC * DSC);
        int rem = dm - di * DSC * DSC;
        int dj  = rem / DSC;
        int dk  = rem - dj * DSC;
        baseRow[tid] = ((2 * di) * DD + 2 * dj) * DD + 2 * dk;
    }
    __syncthreads();

    // loader role: 16 threads per row, one float4 each -> fully coalesced lines
    const int q  = tid & 15;           // float4 index within 256B row
    const int rg = tid >> 4;           // 0..7; rows rg + g*8
    int rb[8];
    #pragma unroll
    for (int g = 0; g < 8; g++) rb[g] = baseRow[rg + g * 8];

    // ldmatrix A address components
    const uint32_t aOff0 = (uint32_t)((wm * 32 + (l & 15)) * APITCH + (l >> 4) * 8) * 2;
    const uint32_t aOff1 = aOff0 + 16 * APB;

    float acc0[4][4], acc1[4][4];
    #pragma unroll
    for (int n = 0; n < 4; n++)
        #pragma unroll
        for (int i = 0; i < 4; i++) { acc0[n][i] = 0.0f; acc1[n][i] = 0.0f; }

    // prefetch chunk 0 (octant 0: offs = 0)
    float4 pf[8];
    #pragma unroll
    for (int g = 0; g < 8; g++)
        pf[g] = *(const float4*)(in_data + (size_t)rb[g] * CH + q * 4);

    const uint2* wfrag = (const uint2*)g_wf;   // index: ((s*4+kb)*8 + jn)*32 + lane

    for (int s = 0; s < NCHUNK; s++) {
        const uint32_t abase = sbase + ((s & 1) ? OFF_A1 : OFF_A0);

        // ---- fill: fp32->fp16 convert + STS.64 into buf[s&1] ----
        {
            char* dA = smem + ((s & 1) ? OFF_A1 : OFF_A0) + q * 8;
            #pragma unroll
            for (int g = 0; g < 8; g++) {
                uint2 h;
                h.x = cvt2(pf[g].x, pf[g].y);
                h.y = cvt2(pf[g].z, pf[g].w);
                *(uint2*)(dA + (rg + g * 8) * APB) = h;
            }
        }

        // ---- issue next chunk's loads BEFORE the barrier: latency overlaps
        //      the barrier wait + the whole MMA block below ----
        if (s + 1 < NCHUNK) {
            const int sn = s + 1;
            const int offs = ((sn >> 2) & 1) * (DD * DD) + ((sn >> 1) & 1) * DD + (sn & 1);
            #pragma unroll
            for (int g = 0; g < 8; g++)
                pf[g] = *(const float4*)(in_data + (size_t)(rb[g] + offs) * CH + q * 4);
        }
        __syncthreads();   // single barrier per chunk (double buffered)

        // ---- compute: 4 k16-steps, warp tile 32x32 ----
        #pragma unroll
        for (int kb = 0; kb < 4; kb++) {
            uint32_t a0[4], a1[4];
            ldm_x4(a0, abase + aOff0 + kb * 32);
            ldm_x4(a1, abase + aOff1 + kb * 32);

            uint2 w2[4];
            #pragma unroll
            for (int n = 0; n < 4; n++)
                w2[n] = __ldg(&wfrag[(((s * 4 + kb) * 8) + wn * 4 + n) * 32 + l]);

            #pragma unroll
            for (int n = 0; n < 4; n++) {
                mma_fp16(acc0[n], a0, (const uint32_t*)&w2[n]);
                mma_fp16(acc1[n], a1, (const uint32_t*)&w2[n]);
            }
        }
    }

    // ---- epilogue: direct float2 stores ----
    const int r0 = blockIdx.x * MT + wm * 32 + (l >> 2);
    const int cb = wn * 32 + (l & 3) * 2;
    #pragma unroll
    for (int n = 0; n < 4; n++) {
        *(float2*)&out[(size_t)r0 * 64 + cb + n * 8]        = make_float2(acc0[n][0], acc0[n][1]);
        *(float2*)&out[(size_t)(r0 + 8) * 64 + cb + n * 8]  = make_float2(acc0[n][2], acc0[n][3]);
        *(float2*)&out[(size_t)(r0 + 16) * 64 + cb + n * 8] = make_float2(acc1[n][0], acc1[n][1]);
        *(float2*)&out[(size_t)(r0 + 24) * 64 + cb + n * 8] = make_float2(acc1[n][2], acc1[n][3]);
    }
}

extern "C" void kernel_launch(void* const* d_in, const int* in_sizes, int n_in,
                              void* d_out, int out_size) {
    const float* in_data = (const float*)d_in[0];
    // d_in[1] = ijk: canonical lexicographic order by construction -> unused
    const float* w_out   = (const float*)d_in[2];
    float*       out     = (float*)d_out;

    cudaFuncSetAttribute(ds_fp16_mma_kernel,
                         cudaFuncAttributeMaxDynamicSharedMemorySize, SMEM_TOTAL);
    conv_wf_kernel<<<64, 256>>>(w_out);
    ds_fp16_mma_kernel<<<NCTA, 128, SMEM_TOTAL>>>(in_data, out);
}